// round 3
// baseline (speedup 1.0000x reference)
#include <cuda_runtime.h>
#include <cuda_bf16.h>

// out[b, i*64 + j] = x[b, i] * W[i, j]
// B=8192, L=100, E=64. Output row = 6400 floats = 1600 float4.
//
// 320 threads/block; thread t owns float4 columns {t, t+320, ..., t+1280} (5 of 1600).
// W float4s for those columns are loaded ONCE into registers, then the block
// streams ROWS_PER_BLOCK batch rows: 5 independent x loads + 5 independent
// STG.128 per row, no cross-iteration dependence -> deep MLP, store pipe full.

#define L_DIM          100
#define ROW_F4         1600
#define THREADS        320
#define F4_PER_THREAD  5        // 1600 / 320
#define ROWS_PER_BLOCK 8        // 8192 / 8 = 1024 blocks

__global__ __launch_bounds__(THREADS)
void chem_embed_kernel(const float* __restrict__ x,
                       const float* __restrict__ W,
                       float* __restrict__ out)
{
    const int t = threadIdx.x;

    // Per-thread persistent W tile + x index per owned column.
    float4 w[F4_PER_THREAD];
    int    xi[F4_PER_THREAD];
#pragma unroll
    for (int u = 0; u < F4_PER_THREAD; u++) {
        const int r = t + u * THREADS;          // float4 column in [0,1600)
        w[u]  = __ldg(&((const float4*)W)[r]);  // W is [100,64] = 1600 float4
        xi[u] = r >> 4;                         // position index i = r / 16
    }

    const int b0 = blockIdx.x * ROWS_PER_BLOCK;

#pragma unroll
    for (int row = 0; row < ROWS_PER_BLOCK; row++) {
        const int b = b0 + row;
        const float* __restrict__ xr = x + (long long)b * L_DIM;

        // Batch the 5 x loads (independent -> front-batched by ptxas).
        float xv[F4_PER_THREAD];
#pragma unroll
        for (int u = 0; u < F4_PER_THREAD; u++)
            xv[u] = __ldg(&xr[xi[u]]);

        float4* __restrict__ orow = ((float4*)out) + (long long)b * ROW_F4;
#pragma unroll
        for (int u = 0; u < F4_PER_THREAD; u++) {
            float4 o;
            o.x = xv[u] * w[u].x;
            o.y = xv[u] * w[u].y;
            o.z = xv[u] * w[u].z;
            o.w = xv[u] * w[u].w;
            orow[t + u * THREADS] = o;          // warp-contiguous STG.128
        }
    }
}

extern "C" void kernel_launch(void* const* d_in, const int* in_sizes, int n_in,
                              void* d_out, int out_size)
{
    const float* x = (const float*)d_in[0];   // [8192, 100]
    const float* W = (const float*)d_in[1];   // [100, 64]
    float* out = (float*)d_out;               // [8192, 1, 6400]

    dim3 grid(8192 / ROWS_PER_BLOCK);         // 1024 blocks
    dim3 block(THREADS);
    chem_embed_kernel<<<grid, block>>>(x, W, out);
}

// round 6
// speedup vs baseline: 1.3322x; 1.3322x over previous
#include <cuda_runtime.h>
#include <cuda_bf16.h>

// out[b, i*64 + j] = x[b, i] * W[i, j]
// B=8192, L=100, E=64. Output row = 6400 floats = 1600 float4.
//
// R5 = R3/R4 experiment (infra failed twice; resubmitting with a 1D grid
// instead of 2D to vary the launch shape, logic identical).
// Thread <-> one float4 column (5 col-groups x 320 threads = 1600 per row),
// unrolled x4 across batch rows b, b+2048, b+4096, b+6144. One W float4 in
// registers, 4 independent x loads, 4 independent coalesced STG.128 ->
// store MLP 4 at ~28 regs, occupancy near the 93.75% cap.

#define L_DIM    100
#define ROW_F4   1600        // 6400 floats / 4
#define THREADS  320
#define COLBLKS  5           // 5 * 320 = 1600 float4 per row
#define BROWS    2048        // 8192 / 4 row-groups
#define UNROLL   4

__global__ __launch_bounds__(THREADS)
void chem_embed_kernel(const float* __restrict__ x,
                       const float* __restrict__ W,
                       float* __restrict__ out)
{
    const int blk = blockIdx.x;           // [0, 5*2048)
    const int cb  = blk % COLBLKS;        // column-group
    const int b0  = blk / COLBLKS;        // base batch row, [0,2048)

    const int r = cb * THREADS + threadIdx.x;   // float4 column, [0,1600)
    const int i = r >> 4;                       // position index (16 float4 each)

    const float4 w4 = __ldg(&((const float4*)W)[r]);

    // 4 independent x loads (front-batched by ptxas -> MLP 4)
    float xv[UNROLL];
#pragma unroll
    for (int u = 0; u < UNROLL; u++)
        xv[u] = __ldg(&x[(long long)(b0 + u * BROWS) * L_DIM + i]);

    // 4 independent fully-coalesced STG.128
#pragma unroll
    for (int u = 0; u < UNROLL; u++) {
        float4 o;
        o.x = xv[u] * w4.x;
        o.y = xv[u] * w4.y;
        o.z = xv[u] * w4.z;
        o.w = xv[u] * w4.w;
        ((float4*)out)[(long long)(b0 + u * BROWS) * ROW_F4 + r] = o;
    }
}

extern "C" void kernel_launch(void* const* d_in, const int* in_sizes, int n_in,
                              void* d_out, int out_size)
{
    const float* x = (const float*)d_in[0];   // [8192, 100]
    const float* W = (const float*)d_in[1];   // [100, 64]
    float* out = (float*)d_out;               // [8192, 1, 6400]

    dim3 grid(COLBLKS * BROWS);               // 10240 blocks, 1D
    dim3 block(THREADS);
    chem_embed_kernel<<<grid, block>>>(x, W, out);
}

// round 7
// speedup vs baseline: 1.5600x; 1.1710x over previous
#include <cuda_runtime.h>
#include <cuda_bf16.h>

// out[b, i*64 + j] = x[b, i] * W[i, j]
// B=8192, L=100, E=64. Output row = 6400 floats = 1600 float4.
//
// R6: push the confirmed store-MLP lever further. Thread <-> one float4
// column (5 col-groups x 320 threads = 1600 per row), unrolled x8 across
// batch rows b, b+1024, ..., b+7168. One W float4 in registers, 8
// independent x loads, 8 independent coalesced STG.128 with .cs streaming
// hint (output is write-once, never re-read).

#define L_DIM    100
#define ROW_F4   1600        // 6400 floats / 4
#define THREADS  320
#define COLBLKS  5           // 5 * 320 = 1600 float4 per row
#define BROWS    1024        // 8192 / 8 row-groups
#define UNROLL   8

__global__ __launch_bounds__(THREADS)
void chem_embed_kernel(const float* __restrict__ x,
                       const float* __restrict__ W,
                       float* __restrict__ out)
{
    const int blk = blockIdx.x;           // [0, 5*1024)
    const int cb  = blk % COLBLKS;        // column-group
    const int b0  = blk / COLBLKS;        // base batch row, [0,1024)

    const int r = cb * THREADS + threadIdx.x;   // float4 column, [0,1600)
    const int i = r >> 4;                       // position index (16 float4 each)

    const float4 w4 = __ldg(&((const float4*)W)[r]);

    // 8 independent x loads (front-batched -> MLP 8)
    float xv[UNROLL];
#pragma unroll
    for (int u = 0; u < UNROLL; u++)
        xv[u] = __ldg(&x[(long long)(b0 + u * BROWS) * L_DIM + i]);

    // 8 independent fully-coalesced streaming STG.128
#pragma unroll
    for (int u = 0; u < UNROLL; u++) {
        float4 o;
        o.x = xv[u] * w4.x;
        o.y = xv[u] * w4.y;
        o.z = xv[u] * w4.z;
        o.w = xv[u] * w4.w;
        __stcs(((float4*)out) + (long long)(b0 + u * BROWS) * ROW_F4 + r, o);
    }
}

extern "C" void kernel_launch(void* const* d_in, const int* in_sizes, int n_in,
                              void* d_out, int out_size)
{
    const float* x = (const float*)d_in[0];   // [8192, 100]
    const float* W = (const float*)d_in[1];   // [100, 64]
    float* out = (float*)d_out;               // [8192, 1, 6400]

    dim3 grid(COLBLKS * BROWS);               // 5120 blocks, 1D
    dim3 block(THREADS);
    chem_embed_kernel<<<grid, block>>>(x, W, out);
}

// round 8
// speedup vs baseline: 1.5630x; 1.0019x over previous
#include <cuda_runtime.h>
#include <cuda_bf16.h>

// out[b, i*64 + j] = x[b, i] * W[i, j]
// B=8192, L=100, E=64. Output row = 6400 floats = 1600 float4.
//
// R7: UNROLL 8->16, and switch to CONTIGUOUS rows per block so every
// store/load offset is a compile-time immediate (row stride 25.6KB fits the
// STG 24-bit imm window; the old 26MB stride did not). 1 base register +
// 16 immediate-offset STG.128 per thread -> deep MLP at low reg count.
// Block owns float4-column group cb and batch rows [b0*16, b0*16+16).

#define L_DIM    100
#define ROW_F4   1600        // 6400 floats / 4
#define THREADS  320
#define COLBLKS  5           // 5 * 320 = 1600 float4 per row
#define UNROLL   16
#define RGROUPS  (8192 / UNROLL)   // 512 row-groups

__global__ __launch_bounds__(THREADS)
void chem_embed_kernel(const float* __restrict__ x,
                       const float* __restrict__ W,
                       float* __restrict__ out)
{
    const int blk = blockIdx.x;            // [0, 5*512)
    const int cb  = blk % COLBLKS;         // column-group
    const int g   = blk / COLBLKS;         // row-group, [0,512)
    const int b0  = g * UNROLL;            // first batch row of this block

    const int r = cb * THREADS + threadIdx.x;   // float4 column, [0,1600)
    const int i = r >> 4;                       // position index (16 float4 each)

    const float4 w4 = __ldg(&((const float4*)W)[r]);

    // 16 independent x loads; single base, immediate offsets u*L_DIM.
    const float* __restrict__ xb = x + (long long)b0 * L_DIM + i;
    float xv[UNROLL];
#pragma unroll
    for (int u = 0; u < UNROLL; u++)
        xv[u] = __ldg(xb + u * L_DIM);

    // 16 independent streaming STG.128; single base, immediate offsets u*ROW_F4.
    float4* __restrict__ ob = ((float4*)out) + (long long)b0 * ROW_F4 + r;
#pragma unroll
    for (int u = 0; u < UNROLL; u++) {
        float4 o;
        o.x = xv[u] * w4.x;
        o.y = xv[u] * w4.y;
        o.z = xv[u] * w4.z;
        o.w = xv[u] * w4.w;
        __stcs(ob + u * ROW_F4, o);
    }
}

extern "C" void kernel_launch(void* const* d_in, const int* in_sizes, int n_in,
                              void* d_out, int out_size)
{
    const float* x = (const float*)d_in[0];   // [8192, 100]
    const float* W = (const float*)d_in[1];   // [100, 64]
    float* out = (float*)d_out;               // [8192, 1, 6400]

    dim3 grid(COLBLKS * RGROUPS);             // 2560 blocks
    dim3 block(THREADS);
    chem_embed_kernel<<<grid, block>>>(x, W, out);
}